// round 1
// baseline (speedup 1.0000x reference)
#include <cuda_runtime.h>
#include <cstdint>

// ---------------- SLAYER constants (double -> f32, matching python float math) ----
#define C2A 1.8096748360719190f   // 2*exp(-0.1)
#define CA2 0.8187307530779818f   // exp(-0.2)
#define CB1 0.2459603111156949f   // e*exp(-0.1)/10

// ---------------- scratch (static device memory; no allocation) -------------------
#define UMAX 52428800  // 100*4*32*64*64
__device__ float g_u[UMAX];
__device__ float g_sa[UMAX];
__device__ float g_sb[UMAX];
__device__ float g_part[4 * 400 * 512];

// ---------------- fused psp + spike scan (generic, u already materialized) --------
__global__ void scan_k(const float* __restrict__ u, float* __restrict__ s, int N) {
    int n = blockIdx.x * blockDim.x + threadIdx.x;
    if (n >= N) return;
    float p1 = 0.f, p2 = 0.f, cp = 0.f, r1 = 0.f, r2 = 0.f, sp = 0.f;
    for (int t = 0; t < 100; t++) {
        float c  = u[(size_t)t * N + n];
        float uu = C2A * p1 - CA2 * p2 + CB1 * cp;
        float yy = C2A * r1 - CA2 * r2 + CB1 * sp;
        float ss = (uu - 20.0f * yy >= 10.0f) ? 1.0f : 0.0f;
        s[(size_t)t * N + n] = ss;
        p2 = p1; p1 = uu; cp = c;
        r2 = r1; r1 = yy; sp = ss;
    }
}

// ---------------- SP0: pool(2x2)*11 on raw input ([B,C,128,128,T] layout) + scan --
__global__ void scan_in_k(const float* __restrict__ sin, float* __restrict__ sout) {
    const int N = 32768;  // 4*2*64*64
    int n = blockIdx.x * blockDim.x + threadIdx.x;
    if (n >= N) return;
    int w = n & 63, h = (n >> 6) & 63, c = (n >> 12) & 1, b = n >> 13;
    const float* p0 = sin + ((size_t)((b * 2 + c) * 128 + 2 * h) * 128 + 2 * w) * 100;
    const float* p1 = p0 + 100;
    const float* p2 = p0 + 12800;
    const float* p3 = p2 + 100;
    float a1 = 0.f, a2 = 0.f, cp = 0.f, r1 = 0.f, r2 = 0.f, sp = 0.f;
    for (int t = 0; t < 100; t++) {
        float xv = 11.0f * (p0[t] + p1[t] + p2[t] + p3[t]);
        float uu = C2A * a1 - CA2 * a2 + CB1 * cp;
        float yy = C2A * r1 - CA2 * r2 + CB1 * sp;
        float ss = (uu - 20.0f * yy >= 10.0f) ? 1.0f : 0.0f;
        sout[(size_t)t * N + n] = ss;
        a2 = a1; a1 = uu; cp = xv;
        r2 = r1; r1 = yy; sp = ss;
    }
}

// ---------------- fused pool(2x2)*11 + scan (internal [tb][C][2H][2W] spikes) -----
template <int C, int H, int W>
__global__ void scan_pool_k(const float* __restrict__ sin, float* __restrict__ sout) {
    constexpr int N = 4 * C * H * W;
    int n = blockIdx.x * blockDim.x + threadIdx.x;
    if (n >= N) return;
    int w = n % W, h = (n / W) % H, c = (n / (W * H)) % C, b = n / (W * H * C);
    const int istride = 4 * C * 4 * H * W;  // per-t stride of input buffer
    const float* base = sin + (size_t)(((b * C + c) * (2 * H) + 2 * h) * (2 * W) + 2 * w);
    float a1 = 0.f, a2 = 0.f, cp = 0.f, r1 = 0.f, r2 = 0.f, sp = 0.f;
    for (int t = 0; t < 100; t++) {
        const float* p = base + (size_t)t * istride;
        float xv = 11.0f * (p[0] + p[1] + p[2 * W] + p[2 * W + 1]);
        float uu = C2A * a1 - CA2 * a2 + CB1 * cp;
        float yy = C2A * r1 - CA2 * r2 + CB1 * sp;
        float ss = (uu - 20.0f * yy >= 10.0f) ? 1.0f : 0.0f;
        sout[(size_t)t * N + n] = ss;
        a2 = a1; a1 = uu; cp = xv;
        r2 = r1; r1 = yy; sp = ss;
    }
}

// ---------------- direct conv, per image, [tb][C][H][W] layout --------------------
// block: (TILE/2)^2 threads, each thread computes a 2x2 pixel group for OCB out chans
template <int IC, int OC, int HH, int WW, int K, int OCB, int ICB, int TILE>
__global__ void __launch_bounds__((TILE / 2) * (TILE / 2))
conv_k(const float* __restrict__ x, const float* __restrict__ wt, float* __restrict__ y) {
    constexpr int PAD = K / 2, TH = TILE / 2, NT = TH * TH, SW = TILE + K - 1;
    __shared__ float xs[ICB][SW][SW];
    __shared__ float ws[OCB][ICB][K * K];
    const int tid = threadIdx.x;
    const int tx = tid % TH, ty = tid / TH;
    constexpr int tilesx = WW / TILE;
    const int tx0 = (blockIdx.x % tilesx) * TILE, ty0 = (blockIdx.x / tilesx) * TILE;
    const int ocg = blockIdx.y * OCB;
    const float* xb = x + (size_t)blockIdx.z * IC * HH * WW;

    float acc[OCB * 4];
#pragma unroll
    for (int i = 0; i < OCB * 4; i++) acc[i] = 0.f;

    for (int icc = 0; icc < IC; icc += ICB) {
        for (int idx = tid; idx < ICB * SW * SW; idx += NT) {
            int ic = idx / (SW * SW);
            int r = idx - ic * SW * SW;
            int yy = r / SW, xx = r - yy * SW;
            int gy = ty0 + yy - PAD, gx = tx0 + xx - PAD;
            float v = 0.f;
            if (gy >= 0 && gy < HH && gx >= 0 && gx < WW)
                v = xb[(size_t)(icc + ic) * HH * WW + gy * WW + gx];
            xs[ic][yy][xx] = v;
        }
        for (int idx = tid; idx < OCB * ICB * K * K; idx += NT) {
            int o = idx / (ICB * K * K);
            int r = idx - o * ICB * K * K;
            int ic = r / (K * K), kk = r - ic * (K * K);
            ws[o][ic][kk] = wt[((size_t)(ocg + o) * IC + icc + ic) * K * K + kk];
        }
        __syncthreads();
        for (int ic = 0; ic < ICB; ic++) {
#pragma unroll
            for (int kh = 0; kh < K; kh++) {
#pragma unroll
                for (int kw = 0; kw < K; kw++) {
                    float x00 = xs[ic][ty + kh][tx + kw];
                    float x01 = xs[ic][ty + kh][tx + TH + kw];
                    float x10 = xs[ic][ty + TH + kh][tx + kw];
                    float x11 = xs[ic][ty + TH + kh][tx + TH + kw];
#pragma unroll
                    for (int o = 0; o < OCB; o++) {
                        float wv = ws[o][ic][kh * K + kw];
                        acc[o * 4 + 0] += x00 * wv;
                        acc[o * 4 + 1] += x01 * wv;
                        acc[o * 4 + 2] += x10 * wv;
                        acc[o * 4 + 3] += x11 * wv;
                    }
                }
            }
        }
        __syncthreads();
    }
    float* yb = y + ((size_t)blockIdx.z * OC + ocg) * HH * WW;
#pragma unroll
    for (int o = 0; o < OCB; o++) {
        size_t p = (size_t)o * HH * WW + (size_t)(ty0 + ty) * WW + (tx0 + tx);
        yb[p] = acc[o * 4 + 0];
        yb[p + TH] = acc[o * 4 + 1];
        yb[p + (size_t)TH * WW] = acc[o * 4 + 2];
        yb[p + (size_t)TH * WW + TH] = acc[o * 4 + 3];
    }
}

// ---------------- SF4a GEMM: [400 x 8192] * [8192 -> 512], split-K=4 --------------
__global__ void __launch_bounds__(256)
gemm4a_k(const float* __restrict__ x, const float* __restrict__ w, float* __restrict__ part) {
    __shared__ float xs[16][64];
    __shared__ float ws[16][64];
    const int tid = threadIdx.x;
    const int tm = tid % 16, tn = tid / 16;
    const int bm0 = blockIdx.x * 64, bn0 = blockIdx.y * 64;
    const int k0b = blockIdx.z * 2048;
    float acc[16];
#pragma unroll
    for (int i = 0; i < 16; i++) acc[i] = 0.f;
    const int lrow = tid >> 2, lc4 = (tid & 3) * 4;

    for (int k0 = k0b; k0 < k0b + 2048; k0 += 16) {
        int m = bm0 + lrow;
        float4 xv = make_float4(0.f, 0.f, 0.f, 0.f);
        if (m < 400) xv = *reinterpret_cast<const float4*>(x + (size_t)m * 8192 + k0 + lc4);
        xs[lc4 + 0][lrow] = xv.x; xs[lc4 + 1][lrow] = xv.y;
        xs[lc4 + 2][lrow] = xv.z; xs[lc4 + 3][lrow] = xv.w;
        float4 wv = *reinterpret_cast<const float4*>(w + (size_t)(bn0 + lrow) * 8192 + k0 + lc4);
        ws[lc4 + 0][lrow] = wv.x; ws[lc4 + 1][lrow] = wv.y;
        ws[lc4 + 2][lrow] = wv.z; ws[lc4 + 3][lrow] = wv.w;
        __syncthreads();
#pragma unroll
        for (int kk = 0; kk < 16; kk++) {
            float4 a = *reinterpret_cast<const float4*>(&xs[kk][tm * 4]);
            float4 b = *reinterpret_cast<const float4*>(&ws[kk][tn * 4]);
            acc[0]  += a.x * b.x; acc[1]  += a.x * b.y; acc[2]  += a.x * b.z; acc[3]  += a.x * b.w;
            acc[4]  += a.y * b.x; acc[5]  += a.y * b.y; acc[6]  += a.y * b.z; acc[7]  += a.y * b.w;
            acc[8]  += a.z * b.x; acc[9]  += a.z * b.y; acc[10] += a.z * b.z; acc[11] += a.z * b.w;
            acc[12] += a.w * b.x; acc[13] += a.w * b.y; acc[14] += a.w * b.z; acc[15] += a.w * b.w;
        }
        __syncthreads();
    }
    float* pb = part + (size_t)blockIdx.z * 204800;
#pragma unroll
    for (int i = 0; i < 4; i++) {
        int m = bm0 + tm * 4 + i;
        if (m < 400) {
            float4 v = make_float4(acc[i * 4 + 0], acc[i * 4 + 1], acc[i * 4 + 2], acc[i * 4 + 3]);
            *reinterpret_cast<float4*>(pb + (size_t)m * 512 + bn0 + tn * 4) = v;
        }
    }
}

__global__ void reduce4_k(const float* __restrict__ part, float* __restrict__ u) {
    int i = blockIdx.x * blockDim.x + threadIdx.x;
    if (i < 204800)
        u[i] = ((part[i] + part[204800 + i]) + part[409600 + i]) + part[614400 + i];
}

// ---------------- SF4b GEMM: [400 x 512] * [512 -> 11] ----------------------------
__global__ void gemm4b_k(const float* __restrict__ x, const float* __restrict__ w,
                         float* __restrict__ u) {
    int tb = blockIdx.x;
    int wid = threadIdx.x >> 5, lid = threadIdx.x & 31;  // 11 warps
    const float* xr = x + (size_t)tb * 512;
    const float* wr = w + (size_t)wid * 512;
    float s = 0.f;
    for (int k = lid; k < 512; k += 32) s += xr[k] * wr[k];
#pragma unroll
    for (int off = 16; off; off >>= 1) s += __shfl_xor_sync(0xffffffffu, s, off);
    if (lid == 0) u[tb * 11 + wid] = s;
}

// ---------------- final scan: u4b [t][b*11+o] -> d_out [b][11][t] ------------------
__global__ void scan_out_k(const float* __restrict__ u, float* __restrict__ out) {
    int n = threadIdx.x;
    if (n >= 44) return;
    int b = n / 11, o = n % 11;
    float a1 = 0.f, a2 = 0.f, cp = 0.f, r1 = 0.f, r2 = 0.f, sp = 0.f;
    for (int t = 0; t < 100; t++) {
        float c  = u[t * 44 + n];
        float uu = C2A * a1 - CA2 * a2 + CB1 * cp;
        float yy = C2A * r1 - CA2 * r2 + CB1 * sp;
        float ss = (uu - 20.0f * yy >= 10.0f) ? 1.0f : 0.0f;
        out[(b * 11 + o) * 100 + t] = ss;
        a2 = a1; a1 = uu; cp = c;
        r2 = r1; r1 = yy; sp = ss;
    }
}

// ---------------- driver ----------------------------------------------------------
extern "C" void kernel_launch(void* const* d_in, const int* in_sizes, int n_in,
                              void* d_out, int out_size) {
    const float* s_in = (const float*)d_in[0];
    const float* w1   = (const float*)d_in[1];
    const float* w2   = (const float*)d_in[2];
    const float* w3   = (const float*)d_in[3];
    const float* wf4a = (const float*)d_in[4];
    const float* wf4b = (const float*)d_in[5];
    float* out = (float*)d_out;

    float *u, *sa, *sb, *pp;
    cudaGetSymbolAddress((void**)&u, g_u);
    cudaGetSymbolAddress((void**)&sa, g_sa);
    cudaGetSymbolAddress((void**)&sb, g_sb);
    cudaGetSymbolAddress((void**)&pp, g_part);

    // SP0: pool raw input + scan -> sa : [tb][2][64][64]
    scan_in_k<<<128, 256>>>(s_in, sa);
    // SC1: conv 5x5 -> u : [tb][32][64][64]; scan -> sb
    conv_k<2, 32, 64, 64, 5, 16, 2, 32><<<dim3(4, 2, 400), 256>>>(sa, w1, u);
    scan_k<<<2048, 256>>>(u, sb, 524288);
    // SP1: pool+scan -> sa : [tb][32][32][32]
    scan_pool_k<32, 32, 32><<<512, 256>>>(sb, sa);
    // SC2: conv 3x3 -> u : [tb][64][32][32]; scan -> sb
    conv_k<32, 64, 32, 32, 3, 16, 8, 32><<<dim3(1, 4, 400), 256>>>(sa, w2, u);
    scan_k<<<1024, 256>>>(u, sb, 262144);
    // SP2: pool+scan -> sa : [tb][64][16][16]
    scan_pool_k<64, 16, 16><<<256, 256>>>(sb, sa);
    // SC3: conv 3x3 -> u : [tb][128][16][16]; scan -> sb
    conv_k<64, 128, 16, 16, 3, 16, 16, 16><<<dim3(1, 8, 400), 64>>>(sa, w3, u);
    scan_k<<<512, 256>>>(u, sb, 131072);
    // SP3: pool+scan -> sa : [tb][128][8][8] == [tb][8192]
    scan_pool_k<128, 8, 8><<<128, 256>>>(sb, sa);
    // SF4a: GEMM split-K + reduce -> u : [tb][512]; scan -> sb
    gemm4a_k<<<dim3(7, 8, 4), 256>>>(sa, wf4a, pp);
    reduce4_k<<<800, 256>>>(pp, u);
    scan_k<<<8, 256>>>(u, sb, 2048);
    // SF4b: GEMM -> u : [tb][11]; final scan -> d_out [4][11][100]
    gemm4b_k<<<400, 352>>>(sb, wf4b, u);
    scan_out_k<<<1, 64>>>(u, out);
}

// round 2
// speedup vs baseline: 1.2146x; 1.2146x over previous
#include <cuda_runtime.h>
#include <cstdint>

// ---------------- SLAYER constants (double -> f32) --------------------------------
#define C2A 1.8096748360719190f   // 2*exp(-0.1)
#define CA2 0.8187307530779818f   // exp(-0.2)
#define CB1 0.2459603111156949f   // e*exp(-0.1)/10

// ---------------- scratch (static device memory; no allocation) -------------------
#define UMAX 52428800  // 100*4*32*64*64 floats
__device__ float g_u[UMAX];
__device__ unsigned char g_s8a[13107200];
__device__ unsigned char g_s8b[13107200];
__device__ float g_part[4 * 400 * 512];

// ---------------- f32x2 helpers ---------------------------------------------------
__device__ __forceinline__ unsigned long long pk2(float a, float b) {
    unsigned long long r;
    asm("mov.b64 %0, {%1,%2};" : "=l"(r) : "f"(a), "f"(b));
    return r;
}
__device__ __forceinline__ unsigned long long fma2(unsigned long long a,
                                                   unsigned long long b,
                                                   unsigned long long c) {
    unsigned long long d;
    asm("fma.rn.f32x2 %0, %1, %2, %3;" : "=l"(d) : "l"(a), "l"(b), "l"(c));
    return d;
}
__device__ __forceinline__ float2 upk(unsigned long long v) {
    float2 r;
    asm("mov.b64 {%0,%1}, %2;" : "=f"(r.x), "=f"(r.y) : "l"(v));
    return r;
}

// ---------------- SP0: pool(2x2)*11 on raw input ([B,C,128,128,T]) + scan ---------
__global__ void scan_in_k(const float* __restrict__ sin, unsigned char* __restrict__ sout) {
    const int N = 32768;  // 4*2*64*64
    int n = blockIdx.x * blockDim.x + threadIdx.x;
    if (n >= N) return;
    int w = n & 63, h = (n >> 6) & 63, c = (n >> 12) & 1, b = n >> 13;
    const float* p0 = sin + ((size_t)((b * 2 + c) * 128 + 2 * h) * 128 + 2 * w) * 100;
    const float* p1 = p0 + 100;
    const float* p2 = p0 + 12800;
    const float* p3 = p2 + 100;
    float a1 = 0.f, a2 = 0.f, cp = 0.f, r1 = 0.f, r2 = 0.f, sp = 0.f;
    for (int t = 0; t < 100; t++) {
        float xv = 11.0f * (p0[t] + p1[t] + p2[t] + p3[t]);
        float uu = C2A * a1 - CA2 * a2 + CB1 * cp;
        float yy = C2A * r1 - CA2 * r2 + CB1 * sp;
        float ss = (uu - 20.0f * yy >= 10.0f) ? 1.0f : 0.0f;
        sout[(size_t)t * N + n] = (unsigned char)ss;
        a2 = a1; a1 = uu; cp = xv;
        r2 = r1; r1 = yy; sp = ss;
    }
}

// ---------------- fused: conv-neuron scan (2x2 group) + pool + pooled-neuron scan --
// input u: [z=(t*4+b)][C][2H][2W] fp32, output pooled spikes: [t][b][C][H][W] uint8
template <int C, int H, int W>
__global__ void scanpool_k(const float* __restrict__ u, unsigned char* __restrict__ s) {
    constexpr int N = 4 * C * H * W;
    int n = blockIdx.x * blockDim.x + threadIdx.x;
    if (n >= N) return;
    int w = n % W, h = (n / W) % H, c = (n / (W * H)) % C, b = n / (W * H * C);
    const float* base = u + (size_t)(((b * C + c) * (2 * H) + 2 * h) * (2 * W) + 2 * w);
    constexpr size_t ST = (size_t)16 * C * H * W;  // per-t stride (4 images)
    float y1[4], y2[4], xp[4], r1[4], r2[4], sp[4];
#pragma unroll
    for (int i = 0; i < 4; i++) { y1[i] = y2[i] = xp[i] = r1[i] = r2[i] = sp[i] = 0.f; }
    float py1 = 0.f, py2 = 0.f, pxp = 0.f, pr1 = 0.f, pr2 = 0.f, psp = 0.f;
    for (int t = 0; t < 100; t++) {
        float2 ra = *(const float2*)(base);
        float2 rb = *(const float2*)(base + 2 * W);
        float xin[4] = {ra.x, ra.y, rb.x, rb.y};
        float ssum = 0.f;
#pragma unroll
        for (int i = 0; i < 4; i++) {
            float yy = C2A * y1[i] - CA2 * y2[i] + CB1 * xp[i];
            float rr = C2A * r1[i] - CA2 * r2[i] + CB1 * sp[i];
            float si = (yy - 20.0f * rr >= 10.0f) ? 1.0f : 0.0f;
            y2[i] = y1[i]; y1[i] = yy; xp[i] = xin[i];
            r2[i] = r1[i]; r1[i] = rr; sp[i] = si;
            ssum += si;
        }
        float pu = C2A * py1 - CA2 * py2 + CB1 * pxp;
        float pr = C2A * pr1 - CA2 * pr2 + CB1 * psp;
        float ps = (pu - 20.0f * pr >= 10.0f) ? 1.0f : 0.0f;
        py2 = py1; py1 = pu; pxp = 11.0f * ssum;
        pr2 = pr1; pr1 = pr; psp = ps;
        s[(size_t)t * N + n] = (unsigned char)ps;
        base += ST;
    }
}

// ---------------- plain psp+spike scan (fp32 u -> u8 spikes) -----------------------
__global__ void scan_k(const float* __restrict__ u, unsigned char* __restrict__ s, int N) {
    int n = blockIdx.x * blockDim.x + threadIdx.x;
    if (n >= N) return;
    float p1 = 0.f, p2 = 0.f, cp = 0.f, r1 = 0.f, r2 = 0.f, sp = 0.f;
    for (int t = 0; t < 100; t++) {
        float c  = u[(size_t)t * N + n];
        float uu = C2A * p1 - CA2 * p2 + CB1 * cp;
        float yy = C2A * r1 - CA2 * r2 + CB1 * sp;
        float ss = (uu - 20.0f * yy >= 10.0f) ? 1.0f : 0.0f;
        s[(size_t)t * N + n] = (unsigned char)ss;
        p2 = p1; p1 = uu; cp = c;
        r2 = r1; r1 = yy; sp = ss;
    }
}

// ---------------- direct conv, u8 spikes in, fp32 u out, f32x2 FFMA ----------------
// thread tile: 8 pixels (2 rows x 4 cols, strided) x 16 out-channels (8 f32x2 pairs)
template <int IC, int OC, int HH, int WW, int K, int ICB, int TX, int TY, int XST>
__global__ void __launch_bounds__((TX / 4) * (TY / 2))
conv_k(const unsigned char* __restrict__ x, const float* __restrict__ wt,
       float* __restrict__ y) {
    constexpr int PAD = K / 2, TPX = TX / 4, TPY = TY / 2, NT = TPX * TPY;
    constexpr int SW = TX + K - 1, SH = TY + K - 1;
    __shared__ __align__(16) float xs[ICB * SH * XST];
    __shared__ __align__(16) float ws[ICB * K * K * 16];
    const int tid = threadIdx.x;
    const int tx = tid % TPX, ty = tid / TPX;
    constexpr int tilesx = WW / TX;
    const int tx0 = (blockIdx.x % tilesx) * TX, ty0 = (blockIdx.x / tilesx) * TY;
    const int ocg = blockIdx.y * 16;
    const unsigned char* xb = x + (size_t)blockIdx.z * IC * HH * WW;

    unsigned long long acc[8][8];
#pragma unroll
    for (int p = 0; p < 8; p++)
#pragma unroll
        for (int o = 0; o < 8; o++) acc[p][o] = 0ULL;

    for (int icc = 0; icc < IC; icc += ICB) {
        for (int idx = tid; idx < ICB * SH * SW; idx += NT) {
            int ic = idx / (SH * SW);
            int r = idx - ic * SH * SW;
            int yy = r / SW, xx = r - yy * SW;
            int gy = ty0 + yy - PAD, gx = tx0 + xx - PAD;
            float v = 0.f;
            if (gy >= 0 && gy < HH && gx >= 0 && gx < WW)
                v = (float)xb[(size_t)(icc + ic) * HH * WW + gy * WW + gx];
            xs[(ic * SH + yy) * XST + xx] = v;
        }
        for (int idx = tid; idx < ICB * K * K * 16; idx += NT) {
            int o = idx & 15;
            int r = idx >> 4;
            int ic = r / (K * K), kk = r - ic * (K * K);
            ws[idx] = wt[((size_t)(ocg + o) * IC + icc + ic) * (K * K) + kk];
        }
        __syncthreads();
        for (int ic = 0; ic < ICB; ic++) {
#pragma unroll
            for (int kh = 0; kh < K; kh++) {
#pragma unroll
                for (int kw = 0; kw < K; kw++) {
                    unsigned long long xp[8];
#pragma unroll
                    for (int r = 0; r < 2; r++)
#pragma unroll
                        for (int c = 0; c < 4; c++) {
                            float v = xs[(ic * SH + ty + r * TPY + kh) * XST + tx + c * TPX + kw];
                            xp[r * 4 + c] = pk2(v, v);
                        }
                    const unsigned long long* wq =
                        (const unsigned long long*)&ws[(ic * K * K + kh * K + kw) * 16];
                    unsigned long long wr[8];
#pragma unroll
                    for (int i = 0; i < 8; i++) wr[i] = wq[i];
#pragma unroll
                    for (int p = 0; p < 8; p++)
#pragma unroll
                        for (int o = 0; o < 8; o++)
                            acc[p][o] = fma2(xp[p], wr[o], acc[p][o]);
                }
            }
        }
        __syncthreads();
    }
    float* yb = y + ((size_t)blockIdx.z * OC + ocg) * HH * WW;
#pragma unroll
    for (int p = 0; p < 8; p++) {
        int row = ty0 + ty + (p >> 2) * TPY, col = tx0 + tx + (p & 3) * TPX;
#pragma unroll
        for (int o = 0; o < 8; o++) {
            float2 v = upk(acc[p][o]);
            yb[(size_t)(2 * o) * HH * WW + (size_t)row * WW + col] = v.x;
            yb[(size_t)(2 * o + 1) * HH * WW + (size_t)row * WW + col] = v.y;
        }
    }
}

// ---------------- SF4a GEMM: [400 x 8192](u8) * [8192 -> 512], split-K=4 ----------
__global__ void __launch_bounds__(256)
gemm4a_k(const unsigned char* __restrict__ x, const float* __restrict__ w,
         float* __restrict__ part) {
    __shared__ __align__(16) float xs[16][64];
    __shared__ __align__(16) float ws[16][64];
    const int tid = threadIdx.x;
    const int tm = tid % 16, tn = tid / 16;
    const int bm0 = blockIdx.x * 64, bn0 = blockIdx.y * 64;
    const int k0b = blockIdx.z * 2048;
    unsigned long long acc[4][2];
#pragma unroll
    for (int i = 0; i < 4; i++) { acc[i][0] = 0ULL; acc[i][1] = 0ULL; }
    const int lrow = tid >> 2, lc4 = (tid & 3) * 4;

    for (int k0 = k0b; k0 < k0b + 2048; k0 += 16) {
        int m = bm0 + lrow;
        uchar4 xv = make_uchar4(0, 0, 0, 0);
        if (m < 400) xv = *reinterpret_cast<const uchar4*>(x + (size_t)m * 8192 + k0 + lc4);
        xs[lc4 + 0][lrow] = (float)xv.x; xs[lc4 + 1][lrow] = (float)xv.y;
        xs[lc4 + 2][lrow] = (float)xv.z; xs[lc4 + 3][lrow] = (float)xv.w;
        float4 wv = *reinterpret_cast<const float4*>(w + (size_t)(bn0 + lrow) * 8192 + k0 + lc4);
        ws[lc4 + 0][lrow] = wv.x; ws[lc4 + 1][lrow] = wv.y;
        ws[lc4 + 2][lrow] = wv.z; ws[lc4 + 3][lrow] = wv.w;
        __syncthreads();
#pragma unroll
        for (int kk = 0; kk < 16; kk++) {
            float4 a = *reinterpret_cast<const float4*>(&xs[kk][tm * 4]);
            const unsigned long long* wp =
                reinterpret_cast<const unsigned long long*>(&ws[kk][tn * 4]);
            unsigned long long w0 = wp[0], w1 = wp[1];
            unsigned long long a0 = pk2(a.x, a.x), a1 = pk2(a.y, a.y);
            unsigned long long a2 = pk2(a.z, a.z), a3 = pk2(a.w, a.w);
            acc[0][0] = fma2(a0, w0, acc[0][0]); acc[0][1] = fma2(a0, w1, acc[0][1]);
            acc[1][0] = fma2(a1, w0, acc[1][0]); acc[1][1] = fma2(a1, w1, acc[1][1]);
            acc[2][0] = fma2(a2, w0, acc[2][0]); acc[2][1] = fma2(a2, w1, acc[2][1]);
            acc[3][0] = fma2(a3, w0, acc[3][0]); acc[3][1] = fma2(a3, w1, acc[3][1]);
        }
        __syncthreads();
    }
    float* pb = part + (size_t)blockIdx.z * 204800;
#pragma unroll
    for (int i = 0; i < 4; i++) {
        int m = bm0 + tm * 4 + i;
        if (m < 400) {
            float2 v0 = upk(acc[i][0]), v1 = upk(acc[i][1]);
            float4 v = make_float4(v0.x, v0.y, v1.x, v1.y);
            *reinterpret_cast<float4*>(pb + (size_t)m * 512 + bn0 + tn * 4) = v;
        }
    }
}

__global__ void reduce4_k(const float* __restrict__ part, float* __restrict__ u) {
    int i = blockIdx.x * blockDim.x + threadIdx.x;
    if (i < 204800)
        u[i] = ((part[i] + part[204800 + i]) + part[409600 + i]) + part[614400 + i];
}

// ---------------- SF4b GEMM: [400 x 512](u8) * [512 -> 11] -------------------------
__global__ void gemm4b_k(const unsigned char* __restrict__ x, const float* __restrict__ w,
                         float* __restrict__ u) {
    int tb = blockIdx.x;
    int wid = threadIdx.x >> 5, lid = threadIdx.x & 31;  // 11 warps
    const unsigned char* xr = x + (size_t)tb * 512;
    const float* wr = w + (size_t)wid * 512;
    float s = 0.f;
    for (int k = lid; k < 512; k += 32) s += (float)xr[k] * wr[k];
#pragma unroll
    for (int off = 16; off; off >>= 1) s += __shfl_xor_sync(0xffffffffu, s, off);
    if (lid == 0) u[tb * 11 + wid] = s;
}

// ---------------- final scan: u4b [t][b*11+o] -> d_out [b][11][t] ------------------
__global__ void scan_out_k(const float* __restrict__ u, float* __restrict__ out) {
    int n = threadIdx.x;
    if (n >= 44) return;
    int b = n / 11, o = n % 11;
    float a1 = 0.f, a2 = 0.f, cp = 0.f, r1 = 0.f, r2 = 0.f, sp = 0.f;
    for (int t = 0; t < 100; t++) {
        float c  = u[t * 44 + n];
        float uu = C2A * a1 - CA2 * a2 + CB1 * cp;
        float yy = C2A * r1 - CA2 * r2 + CB1 * sp;
        float ss = (uu - 20.0f * yy >= 10.0f) ? 1.0f : 0.0f;
        out[(b * 11 + o) * 100 + t] = ss;
        a2 = a1; a1 = uu; cp = c;
        r2 = r1; r1 = yy; sp = ss;
    }
}

// ---------------- driver ----------------------------------------------------------
extern "C" void kernel_launch(void* const* d_in, const int* in_sizes, int n_in,
                              void* d_out, int out_size) {
    const float* s_in = (const float*)d_in[0];
    const float* w1   = (const float*)d_in[1];
    const float* w2   = (const float*)d_in[2];
    const float* w3   = (const float*)d_in[3];
    const float* wf4a = (const float*)d_in[4];
    const float* wf4b = (const float*)d_in[5];
    float* out = (float*)d_out;

    float *u, *pp;
    unsigned char *sa, *sb;
    cudaGetSymbolAddress((void**)&u, g_u);
    cudaGetSymbolAddress((void**)&sa, g_s8a);
    cudaGetSymbolAddress((void**)&sb, g_s8b);
    cudaGetSymbolAddress((void**)&pp, g_part);

    // SP0: pool raw input + scan -> sa : [t][b][2][64][64] u8
    scan_in_k<<<128, 256>>>(s_in, sa);
    // SC1: conv 5x5 -> u : [z][32][64][64]
    conv_k<2, 32, 64, 64, 5, 2, 32, 32, 40><<<dim3(4, 2, 400), 128>>>(sa, w1, u);
    // SC1 scan + SP1 pool + scan -> sb : [t][b][32][32][32] u8
    scanpool_k<32, 32, 32><<<512, 256>>>(u, sb);
    // SC2: conv 3x3 -> u : [z][64][32][32]
    conv_k<32, 64, 32, 32, 3, 8, 32, 32, 40><<<dim3(1, 4, 400), 128>>>(sb, w2, u);
    // scan + SP2 -> sa : [t][b][64][16][16] u8
    scanpool_k<64, 16, 16><<<256, 256>>>(u, sa);
    // SC3: conv 3x3 -> u : [z][128][16][16]
    conv_k<64, 128, 16, 16, 3, 8, 16, 16, 20><<<dim3(1, 8, 400), 32>>>(sa, w3, u);
    // scan + SP3 -> sb : [t][b][128][8][8] = [t][b][8192] u8
    scanpool_k<128, 8, 8><<<128, 256>>>(u, sb);
    // SF4a: GEMM split-K + reduce -> u : [z][512]; scan -> sa
    gemm4a_k<<<dim3(7, 8, 4), 256>>>(sb, wf4a, pp);
    reduce4_k<<<800, 256>>>(pp, u);
    scan_k<<<8, 256>>>(u, sa, 2048);
    // SF4b: GEMM -> u : [z][11]; final scan -> d_out [4][11][100]
    gemm4b_k<<<400, 352>>>(sa, wf4b, u);
    scan_out_k<<<1, 64>>>(u, out);
}